// round 12
// baseline (speedup 1.0000x reference)
#include <cuda_runtime.h>

// Problem constants
#define BATCH 2
#define DD 160
#define HH 160
#define WW 160
#define NTOT (BATCH * DD * HH * WW)   // 8192000
#define INV125 (1.0f / 125.0f)

// Tile config: 32(W) x 16(H) tile, 4 voxels/thread (2 rows x 2 cols)
#define TW 32               // tile width (voxels)
#define TPC 16              // pair-columns (TW/2), threadIdx.x
#define TH 16               // tile height (voxels)
#define TRH 8               // thread rows (TH/2), threadIdx.y
#define DCH 20              // depth chunk per block  -> 800 blocks
#define NCHUNK (DD / DCH)   // 8
#define NTHR 128
#define KSLOTS 6            // ceil(720/128)
#define SROWS (TH + 4)      // 20
#define SCOLS (TW + 4)      // 36
#define SCOLSP 38           // float2 stride: even -> every row 16B-aligned
#define SELEMS (SROWS * SCOLS)  // 720

__global__ void __launch_bounds__(NTHR, 4)
lncc_fused(const float* __restrict__ M,
           const float* __restrict__ R,
           float* __restrict__ out) {
    // Double-buffered staging: interleaved (m, r) pairs.   (12.16 KB)
    __shared__ float2 mr2[2][SROWS][SCOLSP];
    // Depth ring: only 4 planes needed (window = Q + current).  (40.96 KB)
    __shared__ float4 hista[4][TH][TPC];                 // {M0,M1,R0,R1}
    __shared__ float4 histb[4][TH][TPC];                 // {MM0,MM1,RR0,RR1}
    __shared__ float2 histc[4][TH][TPC];                 // {MR0,MR1}

    const int tx  = threadIdx.x;          // 0..15 (pair col)
    const int ty  = threadIdx.y;          // 0..7  (row pair)
    const int tid = ty * TPC + tx;        // 0..127
    const int y0  = 2 * ty;               // first output row

    const int w0 = blockIdx.x * TW;
    const int h0 = blockIdx.y * TH;
    const int bz = blockIdx.z;            // b*NCHUNK + chunk
    const int b  = bz >> 3;               // NCHUNK == 8
    const int z0 = (bz & 7) * DCH;

    const size_t vol = (size_t)HH * WW;
    const float* Mb = M + (size_t)b * DD * vol;
    const float* Rb = R + (size_t)b * DD * vol;

    // ---- Loop-invariant staging metadata ----
    int  goff[KSLOTS], soff[KSLOTS];
    bool inb[KSLOTS];
#pragma unroll
    for (int k = 0; k < KSLOTS; k++) {
        const int i = tid + k * NTHR;
        const bool vld = (i < SELEMS);
        int row = 0, col = 0, h = 0, w = 0;
        if (vld) {
            row = i / SCOLS;
            col = i - row * SCOLS;
            h = h0 - 2 + row;
            w = w0 - 2 + col;
        }
        const bool ok = vld & ((unsigned)h < HH) & ((unsigned)w < WW);
        inb[k]  = ok;
        goff[k] = ok ? (h * WW + w) : 0;
        soff[k] = row * SCOLSP + col;
    }

    // Pre-zero both staging buffers (OOB slots stay zero forever).
    {
        float2* const m0f = &mr2[0][0][0];
        for (int i = tid; i < 2 * SROWS * SCOLSP; i += NTHR)
            m0f[i] = make_float2(0.f, 0.f);
    }

    // Zero own ring slots (thread-private; no barrier needed).
#pragma unroll
    for (int j = 0; j < 4; j++) {
#pragma unroll
        for (int g = 0; g < 2; g++) {
            hista[j][y0 + g][tx] = make_float4(0.f, 0.f, 0.f, 0.f);
            histb[j][y0 + g][tx] = make_float4(0.f, 0.f, 0.f, 0.f);
            histc[j][y0 + g][tx] = make_float2(0.f, 0.f);
        }
    }

    // Q = sum of last 4 plane-sums (per row group), in registers.
    float4 q_ab[2], q_cd[2];
    float2 q_e[2];
#pragma unroll
    for (int g = 0; g < 2; g++) {
        q_ab[g] = make_float4(0.f, 0.f, 0.f, 0.f);
        q_cd[g] = make_float4(0.f, 0.f, 0.f, 0.f);
        q_e[g]  = make_float2(0.f, 0.f);
    }

    float acc = 0.f;
    int rp = 0;

    // ---- Prefetch first plane (z0-2) ----
    float pm[KSLOTS], pr[KSLOTS];
    {
        const int z = z0 - 2;
        const bool okz = (z >= 0);
#pragma unroll
        for (int k = 0; k < KSLOTS; k++) {
            float mv = 0.f, rv = 0.f;
            if (okz & inb[k]) {
                const size_t g = (size_t)z * vol + goff[k];
                mv = Mb[g]; rv = Rb[g];
            }
            pm[k] = mv; pr[k] = rv;
        }
    }

    for (int s = 0; s < DCH + 4; s++) {
        const int bi = s & 1;
        float2* const buf = &mr2[bi][0][0];

        // ---- Commit prefetched plane to staging (in-bounds slots only) ----
#pragma unroll
        for (int k = 0; k < KSLOTS; k++)
            if (inb[k]) buf[soff[k]] = make_float2(pm[k], pr[k]);
        __syncthreads();

        // ---- Prefetch next input plane (DRAM latency hidden by compute) ----
        {
            const int z = z0 - 1 + s;
            const bool okz = ((unsigned)z < DD) & (s < DCH + 3);
#pragma unroll
            for (int k = 0; k < KSLOTS; k++) {
                float mv = 0.f, rv = 0.f;
                if (okz & inb[k]) {
                    const size_t g = (size_t)z * vol + goff[k];
                    mv = Mb[g]; rv = Rb[g];
                }
                pm[k] = mv; pr[k] = rv;
            }
        }

        // ---- Direct H x W filter: 6 staging rows feed 2 output rows ----
        float4 sab0 = make_float4(0.f, 0.f, 0.f, 0.f);
        float4 scd0 = make_float4(0.f, 0.f, 0.f, 0.f);
        float2 se0  = make_float2(0.f, 0.f);
        float4 sab1 = sab0;
        float4 scd1 = scd0;
        float2 se1  = se0;
        const int xb = 2 * tx;   // staging col of leftmost halo pair
#pragma unroll
        for (int j = 0; j < 6; j++) {
            const float2* rowp = &mr2[bi][y0 + j][xb];
            const float4 q0 = *(const float4*)(rowp);      // m0 r0 m1 r1
            const float4 q1 = *(const float4*)(rowp + 2);  // m2 r2 m3 r3
            const float4 q2 = *(const float4*)(rowp + 4);  // m4 r4 m5 r5
            const float m0 = q0.x, r0 = q0.y, m1 = q0.z, r1 = q0.w;
            const float m2 = q1.x, r2 = q1.y, m3 = q1.z, r3 = q1.w;
            const float m4 = q2.x, r4 = q2.y, m5 = q2.z, r5 = q2.w;

            // shared middle partials (cols 1..4)
            const float tM  = m1 + m2 + m3 + m4;
            const float tR  = r1 + r2 + r3 + r4;
            const float tMM = fmaf(m1, m1, fmaf(m2, m2, fmaf(m3, m3, m4 * m4)));
            const float tRR = fmaf(r1, r1, fmaf(r2, r2, fmaf(r3, r3, r4 * r4)));
            const float tMR = fmaf(m1, r1, fmaf(m2, r2, fmaf(m3, r3, m4 * r4)));

            const float aM0 = tM + m0,            aM1 = tM + m5;
            const float aR0 = tR + r0,            aR1 = tR + r5;
            const float aMM0 = fmaf(m0, m0, tMM), aMM1 = fmaf(m5, m5, tMM);
            const float aRR0 = fmaf(r0, r0, tRR), aRR1 = fmaf(r5, r5, tRR);
            const float aMR0 = fmaf(m0, r0, tMR), aMR1 = fmaf(m5, r5, tMR);

            if (j < 5) {   // window rows 0..4
                sab0.x += aM0;  sab0.y += aM1;  sab0.z += aR0;  sab0.w += aR1;
                scd0.x += aMM0; scd0.y += aMM1; scd0.z += aRR0; scd0.w += aRR1;
                se0.x  += aMR0; se0.y  += aMR1;
            }
            if (j > 0) {   // window rows 1..5
                sab1.x += aM0;  sab1.y += aM1;  sab1.z += aR0;  sab1.w += aR1;
                scd1.x += aMM0; scd1.y += aMM1; scd1.z += aRR0; scd1.w += aRR1;
                se1.x  += aMR0; se1.y  += aMR1;
            }
        }

        // ---- D window: W = Q + s; Q update via ring of 4; emit ----
#pragma unroll
        for (int g = 0; g < 2; g++) {
            const float4 s_ab = g ? sab1 : sab0;
            const float4 s_cd = g ? scd1 : scd0;
            const float2 s_e  = g ? se1  : se0;
            const float4 oa = hista[rp][y0 + g][tx];   // s from 4 planes ago
            const float4 ob = histb[rp][y0 + g][tx];
            const float2 oc = histc[rp][y0 + g][tx];

            // Full 5-plane window sums.
            const float4 w_ab = make_float4(q_ab[g].x + s_ab.x, q_ab[g].y + s_ab.y,
                                            q_ab[g].z + s_ab.z, q_ab[g].w + s_ab.w);
            const float4 w_cd = make_float4(q_cd[g].x + s_cd.x, q_cd[g].y + s_cd.y,
                                            q_cd[g].z + s_cd.z, q_cd[g].w + s_cd.w);
            const float2 w_e  = make_float2(q_e[g].x + s_e.x, q_e[g].y + s_e.y);

            // Q <- Q + s - old  (sum of last 4 planes)
            q_ab[g].x += s_ab.x - oa.x; q_ab[g].y += s_ab.y - oa.y;
            q_ab[g].z += s_ab.z - oa.z; q_ab[g].w += s_ab.w - oa.w;
            q_cd[g].x += s_cd.x - ob.x; q_cd[g].y += s_cd.y - ob.y;
            q_cd[g].z += s_cd.z - ob.z; q_cd[g].w += s_cd.w - ob.w;
            q_e[g].x  += s_e.x  - oc.x; q_e[g].y  += s_e.y  - oc.y;
            hista[rp][y0 + g][tx] = s_ab;
            histb[rp][y0 + g][tx] = s_cd;
            histc[rp][y0 + g][tx] = s_e;

            if (s >= 4) {
#pragma unroll
                for (int c = 0; c < 2; c++) {
                    const float Mm  = (c ? w_ab.y : w_ab.x) * INV125;
                    const float Rm  = (c ? w_ab.w : w_ab.z) * INV125;
                    const float MMm = (c ? w_cd.y : w_cd.x) * INV125;
                    const float RRm = (c ? w_cd.w : w_cd.z) * INV125;
                    const float MRm = (c ? w_e.y  : w_e.x ) * INV125;

                    const float a   = fmaf(-Mm, Mm, MMm) + 1e-5f;
                    const float bb  = fmaf(-Rm, Rm, RRm) + 1e-5f;
                    const float num = fmaf(-Mm, Rm, MRm);
                    const float ab  = a * bb;
                    const float den = ab * rsqrtf(ab) + 1e-5f; // sqrt(a)*sqrt(b)+eps
                    acc += __fdividef(num, den);
                }
            }
        }

        rp = (rp + 1) & 3;
    }

    // ---- Block reduction (128 threads) + atomic ----
    __shared__ float warp_sums[NTHR / 32];
    float v = acc;
#pragma unroll
    for (int off = 16; off > 0; off >>= 1)
        v += __shfl_xor_sync(0xFFFFFFFFu, v, off);
    if ((tid & 31) == 0) warp_sums[tid >> 5] = v;
    __syncthreads();
    if (tid < 32) {
        float sWS = (tid < NTHR / 32) ? warp_sums[tid] : 0.f;
#pragma unroll
        for (int off = 2; off > 0; off >>= 1)
            sWS += __shfl_xor_sync(0xFFFFFFFFu, sWS, off);
        if (tid == 0)
            atomicAdd(out, -sWS * (1.0f / (float)NTOT));
    }
}

__global__ void lncc_zero_out(float* out) { out[0] = 0.f; }

// ---------------------------------------------------------------------------
extern "C" void kernel_launch(void* const* d_in, const int* in_sizes, int n_in,
                              void* d_out, int out_size) {
    const float* M = (const float*)d_in[0];
    const float* R = (const float*)d_in[1];
    // d_in[2] is the box kernel (ones/125) — folded into INV125.
    float* out = (float*)d_out;

    lncc_zero_out<<<1, 1>>>(out);

    dim3 blk(TPC, TRH, 1);                                  // (16,8) = 128
    dim3 grd(WW / TW, HH / TH, BATCH * NCHUNK);             // (5,10,16) = 800
    lncc_fused<<<grd, blk>>>(M, R, out);
}

// round 13
// speedup vs baseline: 1.0862x; 1.0862x over previous
#include <cuda_runtime.h>

// Problem constants
#define BATCH 2
#define DD 160
#define HH 160
#define WW 160
#define NTOT (BATCH * DD * HH * WW)   // 8192000
#define INV125 (1.0f / 125.0f)

// Tile config: 32(W) x 16(H) tile, 4 voxels/thread (2 rows x 2 cols)
#define TW 32               // tile width (voxels)
#define TPC 16              // pair-columns (TW/2), threadIdx.x
#define TH 16               // tile height (voxels)
#define TRH 8               // thread rows (TH/2), threadIdx.y
#define DCH 40              // depth chunk per block  -> 400 blocks
#define NCHUNK (DD / DCH)   // 4
#define NTHR 128
#define KSLOTS 6            // ceil(720/128)
#define SROWS (TH + 4)      // 20
#define SCOLS (TW + 4)      // 36
#define SCOLSP 38           // float2 stride: even -> every row 16B-aligned
#define SELEMS (SROWS * SCOLS)  // 720

__global__ void __launch_bounds__(NTHR, 3)
lncc_fused(const float* __restrict__ M,
           const float* __restrict__ R,
           float* __restrict__ out) {
    // Double-buffered staging: interleaved (m, r) pairs.   (12.16 KB)
    __shared__ float2 mr2[2][SROWS][SCOLSP];
    // Depth ring (5 planes of HW-filtered sums), packed.   (51.2 KB)
    __shared__ float4 hista[5][TH][TPC];                 // {M0,M1,R0,R1}
    __shared__ float4 histb[5][TH][TPC];                 // {MM0,MM1,RR0,RR1}
    __shared__ float2 histc[5][TH][TPC];                 // {MR0,MR1}

    const int tx  = threadIdx.x;          // 0..15 (pair col)
    const int ty  = threadIdx.y;          // 0..7  (row pair)
    const int tid = ty * TPC + tx;        // 0..127
    const int y0  = 2 * ty;               // first output row

    const int w0 = blockIdx.x * TW;
    const int h0 = blockIdx.y * TH;
    const int bz = blockIdx.z;            // b*NCHUNK + chunk
    const int b  = bz >> 2;               // NCHUNK == 4
    const int z0 = (bz & 3) * DCH;

    const size_t vol = (size_t)HH * WW;
    const float* Mb = M + (size_t)b * DD * vol;
    const float* Rb = R + (size_t)b * DD * vol;

    // ---- Loop-invariant staging metadata ----
    int  goff[KSLOTS], soff[KSLOTS];
    bool inb[KSLOTS];
#pragma unroll
    for (int k = 0; k < KSLOTS; k++) {
        const int i = tid + k * NTHR;
        const bool vld = (i < SELEMS);
        int row = 0, col = 0, h = 0, w = 0;
        if (vld) {
            row = i / SCOLS;
            col = i - row * SCOLS;
            h = h0 - 2 + row;
            w = w0 - 2 + col;
        }
        const bool ok = vld & ((unsigned)h < HH) & ((unsigned)w < WW);
        inb[k]  = ok;
        goff[k] = ok ? (h * WW + w) : 0;
        soff[k] = row * SCOLSP + col;
    }

    // Pre-zero both staging buffers (OOB slots stay zero forever).
    {
        float2* const m0f = &mr2[0][0][0];
        for (int i = tid; i < 2 * SROWS * SCOLSP; i += NTHR)
            m0f[i] = make_float2(0.f, 0.f);
    }

    // Zero own ring slots (thread-private; no barrier needed).
#pragma unroll
    for (int j = 0; j < 5; j++) {
#pragma unroll
        for (int g = 0; g < 2; g++) {
            hista[j][y0 + g][tx] = make_float4(0.f, 0.f, 0.f, 0.f);
            histb[j][y0 + g][tx] = make_float4(0.f, 0.f, 0.f, 0.f);
            histc[j][y0 + g][tx] = make_float2(0.f, 0.f);
        }
    }

    // Running D-window sums (per row group), in registers.
    float4 runs_ab[2], runs_cd[2];
    float2 runs_e[2];
#pragma unroll
    for (int g = 0; g < 2; g++) {
        runs_ab[g] = make_float4(0.f, 0.f, 0.f, 0.f);
        runs_cd[g] = make_float4(0.f, 0.f, 0.f, 0.f);
        runs_e[g]  = make_float2(0.f, 0.f);
    }

    float acc = 0.f;
    int rp = 0;

    // ---- Prefetch first plane (z0-2) ----
    float pm[KSLOTS], pr[KSLOTS];
    {
        const int z = z0 - 2;
        const bool okz = (z >= 0);
#pragma unroll
        for (int k = 0; k < KSLOTS; k++) {
            float mv = 0.f, rv = 0.f;
            if (okz & inb[k]) {
                const size_t g = (size_t)z * vol + goff[k];
                mv = Mb[g]; rv = Rb[g];
            }
            pm[k] = mv; pr[k] = rv;
        }
    }

    for (int s = 0; s < DCH + 4; s++) {
        const int bi = s & 1;
        float2* const buf = &mr2[bi][0][0];

        // ---- Commit prefetched plane to staging (in-bounds slots only) ----
#pragma unroll
        for (int k = 0; k < KSLOTS; k++)
            if (inb[k]) buf[soff[k]] = make_float2(pm[k], pr[k]);
        __syncthreads();

        // ---- Prefetch next input plane (DRAM latency hidden by compute) ----
        {
            const int z = z0 - 1 + s;
            const bool okz = ((unsigned)z < DD) & (s < DCH + 3);
#pragma unroll
            for (int k = 0; k < KSLOTS; k++) {
                float mv = 0.f, rv = 0.f;
                if (okz & inb[k]) {
                    const size_t g = (size_t)z * vol + goff[k];
                    mv = Mb[g]; rv = Rb[g];
                }
                pm[k] = mv; pr[k] = rv;
            }
        }

        // ---- Hoist ring-old loads (LDS latency hidden by row filters) ----
        const float4 oa0 = hista[rp][y0 + 0][tx];
        const float4 ob0 = histb[rp][y0 + 0][tx];
        const float2 oc0 = histc[rp][y0 + 0][tx];
        const float4 oa1 = hista[rp][y0 + 1][tx];
        const float4 ob1 = histb[rp][y0 + 1][tx];
        const float2 oc1 = histc[rp][y0 + 1][tx];

        // ---- Direct H x W filter: accumulate W0 = rows 0..4; save row0;
        //      W1 = W0 - row0 + row5 (single-accumulation restructure) ----
        float4 sab0 = make_float4(0.f, 0.f, 0.f, 0.f);
        float4 scd0 = make_float4(0.f, 0.f, 0.f, 0.f);
        float2 se0  = make_float2(0.f, 0.f);
        float4 sab1, scd1;
        float2 se1;
        float4 r0ab = make_float4(0.f, 0.f, 0.f, 0.f);
        float4 r0cd = make_float4(0.f, 0.f, 0.f, 0.f);
        float2 r0e  = make_float2(0.f, 0.f);
        const int xb = 2 * tx;   // staging col of leftmost halo pair
#pragma unroll
        for (int j = 0; j < 6; j++) {
            const float2* rowp = &mr2[bi][y0 + j][xb];
            const float4 q0 = *(const float4*)(rowp);      // m0 r0 m1 r1
            const float4 q1 = *(const float4*)(rowp + 2);  // m2 r2 m3 r3
            const float4 q2 = *(const float4*)(rowp + 4);  // m4 r4 m5 r5
            const float m0 = q0.x, r0 = q0.y, m1 = q0.z, r1 = q0.w;
            const float m2 = q1.x, r2 = q1.y, m3 = q1.z, r3 = q1.w;
            const float m4 = q2.x, r4 = q2.y, m5 = q2.z, r5 = q2.w;

            // shared middle partials (cols 1..4)
            const float tM  = m1 + m2 + m3 + m4;
            const float tR  = r1 + r2 + r3 + r4;
            const float tMM = fmaf(m1, m1, fmaf(m2, m2, fmaf(m3, m3, m4 * m4)));
            const float tRR = fmaf(r1, r1, fmaf(r2, r2, fmaf(r3, r3, r4 * r4)));
            const float tMR = fmaf(m1, r1, fmaf(m2, r2, fmaf(m3, r3, m4 * r4)));

            const float aM0 = tM + m0,            aM1 = tM + m5;
            const float aR0 = tR + r0,            aR1 = tR + r5;
            const float aMM0 = fmaf(m0, m0, tMM), aMM1 = fmaf(m5, m5, tMM);
            const float aRR0 = fmaf(r0, r0, tRR), aRR1 = fmaf(r5, r5, tRR);
            const float aMR0 = fmaf(m0, r0, tMR), aMR1 = fmaf(m5, r5, tMR);

            if (j == 0) {   // save row 0 for the W1 = W0 - row0 + row5 swap
                r0ab = make_float4(aM0, aM1, aR0, aR1);
                r0cd = make_float4(aMM0, aMM1, aRR0, aRR1);
                r0e  = make_float2(aMR0, aMR1);
            }
            if (j < 5) {    // W0 accumulates rows 0..4
                sab0.x += aM0;  sab0.y += aM1;  sab0.z += aR0;  sab0.w += aR1;
                scd0.x += aMM0; scd0.y += aMM1; scd0.z += aRR0; scd0.w += aRR1;
                se0.x  += aMR0; se0.y  += aMR1;
            } else {        // j == 5: W1 = W0 - row0 + row5
                sab1 = make_float4((sab0.x - r0ab.x) + aM0,
                                   (sab0.y - r0ab.y) + aM1,
                                   (sab0.z - r0ab.z) + aR0,
                                   (sab0.w - r0ab.w) + aR1);
                scd1 = make_float4((scd0.x - r0cd.x) + aMM0,
                                   (scd0.y - r0cd.y) + aMM1,
                                   (scd0.z - r0cd.z) + aRR0,
                                   (scd0.w - r0cd.w) + aRR1);
                se1  = make_float2((se0.x - r0e.x) + aMR0,
                                   (se0.y - r0e.y) + aMR1);
            }
        }

        // ---- Ring D update (incremental window), both row groups ----
#pragma unroll
        for (int g = 0; g < 2; g++) {
            const float4 s_ab = g ? sab1 : sab0;
            const float4 s_cd = g ? scd1 : scd0;
            const float2 s_e  = g ? se1  : se0;
            const float4 oa = g ? oa1 : oa0;
            const float4 ob = g ? ob1 : ob0;
            const float2 oc = g ? oc1 : oc0;
            runs_ab[g].x += s_ab.x - oa.x; runs_ab[g].y += s_ab.y - oa.y;
            runs_ab[g].z += s_ab.z - oa.z; runs_ab[g].w += s_ab.w - oa.w;
            runs_cd[g].x += s_cd.x - ob.x; runs_cd[g].y += s_cd.y - ob.y;
            runs_cd[g].z += s_cd.z - ob.z; runs_cd[g].w += s_cd.w - ob.w;
            runs_e[g].x  += s_e.x  - oc.x; runs_e[g].y  += s_e.y  - oc.y;
            hista[rp][y0 + g][tx] = s_ab;
            histb[rp][y0 + g][tx] = s_cd;
            histc[rp][y0 + g][tx] = s_e;
        }

        rp = (rp == 4) ? 0 : rp + 1;

        // ---- Emit output plane zout = zin - 2 (4 voxels) ----
        if (s >= 4) {
#pragma unroll
            for (int g = 0; g < 2; g++) {
#pragma unroll
                for (int c = 0; c < 2; c++) {
                    const float Mm  = (c ? runs_ab[g].y : runs_ab[g].x) * INV125;
                    const float Rm  = (c ? runs_ab[g].w : runs_ab[g].z) * INV125;
                    const float MMm = (c ? runs_cd[g].y : runs_cd[g].x) * INV125;
                    const float RRm = (c ? runs_cd[g].w : runs_cd[g].z) * INV125;
                    const float MRm = (c ? runs_e[g].y  : runs_e[g].x ) * INV125;

                    const float a   = fmaf(-Mm, Mm, MMm) + 1e-5f;
                    const float bb  = fmaf(-Rm, Rm, RRm) + 1e-5f;
                    const float num = fmaf(-Mm, Rm, MRm);
                    const float ab  = a * bb;
                    const float den = ab * rsqrtf(ab) + 1e-5f; // sqrt(a)*sqrt(b)+eps
                    acc += __fdividef(num, den);
                }
            }
        }
    }

    // ---- Block reduction (128 threads) + atomic ----
    __shared__ float warp_sums[NTHR / 32];
    float v = acc;
#pragma unroll
    for (int off = 16; off > 0; off >>= 1)
        v += __shfl_xor_sync(0xFFFFFFFFu, v, off);
    if ((tid & 31) == 0) warp_sums[tid >> 5] = v;
    __syncthreads();
    if (tid < 32) {
        float sWS = (tid < NTHR / 32) ? warp_sums[tid] : 0.f;
#pragma unroll
        for (int off = 2; off > 0; off >>= 1)
            sWS += __shfl_xor_sync(0xFFFFFFFFu, sWS, off);
        if (tid == 0)
            atomicAdd(out, -sWS * (1.0f / (float)NTOT));
    }
}

__global__ void lncc_zero_out(float* out) { out[0] = 0.f; }

// ---------------------------------------------------------------------------
extern "C" void kernel_launch(void* const* d_in, const int* in_sizes, int n_in,
                              void* d_out, int out_size) {
    const float* M = (const float*)d_in[0];
    const float* R = (const float*)d_in[1];
    // d_in[2] is the box kernel (ones/125) — folded into INV125.
    float* out = (float*)d_out;

    lncc_zero_out<<<1, 1>>>(out);

    dim3 blk(TPC, TRH, 1);                                  // (16,8) = 128
    dim3 grd(WW / TW, HH / TH, BATCH * NCHUNK);             // (5,10,8) = 400
    lncc_fused<<<grd, blk>>>(M, R, out);
}

// round 14
// speedup vs baseline: 1.1777x; 1.0842x over previous
#include <cuda_runtime.h>

// Problem constants
#define BATCH 2
#define DD 160
#define HH 160
#define WW 160
#define NTOT (BATCH * DD * HH * WW)   // 8192000

// Tile config: 32(W) x 16(H) tile, 4 voxels/thread (2 rows x 2 cols)
#define TW 32               // tile width (voxels)
#define TPC 16              // pair-columns (TW/2), threadIdx.x
#define TH 16               // tile height (voxels)
#define TRH 8               // thread rows (TH/2), threadIdx.y
#define DCH 40              // depth chunk per block  -> 400 blocks
#define NCHUNK (DD / DCH)   // 4
#define NTHR 128
#define KSLOTS 6            // ceil(720/128)
#define SROWS (TH + 4)      // 20
#define SCOLS (TW + 4)      // 36
#define SCOLSP 38           // float2 stride: even -> every row 16B-aligned
#define SELEMS (SROWS * SCOLS)  // 720
#define NPAIR 22            // (DCH+4)/2 iterations, 2 planes each

__global__ void __launch_bounds__(NTHR, 3)
lncc_fused(const float* __restrict__ M,
           const float* __restrict__ R,
           float* __restrict__ out) {
    // Quad-buffered staging: 2 iterations x 2 planes. (24.3 KB)
    __shared__ float2 mr2[4][SROWS][SCOLSP];
    // Depth ring (5 planes of HW-filtered sums), packed. (51.2 KB)
    __shared__ float4 hista[5][TH][TPC];                 // {M0,M1,R0,R1}
    __shared__ float4 histb[5][TH][TPC];                 // {MM0,MM1,RR0,RR1}
    __shared__ float2 histc[5][TH][TPC];                 // {MR0,MR1}

    const int tx  = threadIdx.x;          // 0..15 (pair col)
    const int ty  = threadIdx.y;          // 0..7  (row pair)
    const int tid = ty * TPC + tx;        // 0..127
    const int y0  = 2 * ty;               // first output row

    const int w0 = blockIdx.x * TW;
    const int h0 = blockIdx.y * TH;
    const int bz = blockIdx.z;            // b*NCHUNK + chunk
    const int b  = bz >> 2;               // NCHUNK == 4
    const int z0 = (bz & 3) * DCH;

    const size_t vol = (size_t)HH * WW;
    const float* Mb = M + (size_t)b * DD * vol;
    const float* Rb = R + (size_t)b * DD * vol;

    // ---- Loop-invariant staging metadata ----
    int  goff[KSLOTS], soff[KSLOTS];
    bool inb[KSLOTS];
#pragma unroll
    for (int k = 0; k < KSLOTS; k++) {
        const int i = tid + k * NTHR;
        const bool vld = (i < SELEMS);
        int row = 0, col = 0, h = 0, w = 0;
        if (vld) {
            row = i / SCOLS;
            col = i - row * SCOLS;
            h = h0 - 2 + row;
            w = w0 - 2 + col;
        }
        const bool ok = vld & ((unsigned)h < HH) & ((unsigned)w < WW);
        inb[k]  = ok;
        goff[k] = ok ? (h * WW + w) : 0;
        soff[k] = row * SCOLSP + col;
    }

    // Pre-zero all staging buffers (OOB slots stay zero forever).
    {
        float2* const m0f = &mr2[0][0][0];
        for (int i = tid; i < 4 * SROWS * SCOLSP; i += NTHR)
            m0f[i] = make_float2(0.f, 0.f);
    }

    // Zero own ring slots (thread-private; no barrier needed).
#pragma unroll
    for (int j = 0; j < 5; j++) {
#pragma unroll
        for (int g = 0; g < 2; g++) {
            hista[j][y0 + g][tx] = make_float4(0.f, 0.f, 0.f, 0.f);
            histb[j][y0 + g][tx] = make_float4(0.f, 0.f, 0.f, 0.f);
            histc[j][y0 + g][tx] = make_float2(0.f, 0.f);
        }
    }

    // Running D-window sums (per row group), in registers.
    float4 runs_ab[2], runs_cd[2];
    float2 runs_e[2];
#pragma unroll
    for (int g = 0; g < 2; g++) {
        runs_ab[g] = make_float4(0.f, 0.f, 0.f, 0.f);
        runs_cd[g] = make_float4(0.f, 0.f, 0.f, 0.f);
        runs_e[g]  = make_float2(0.f, 0.f);
    }

    float acc = 0.f;
    int rp = 0;

    // ---- Prefetch first two planes (z0-2, z0-1) ----
    float pm0[KSLOTS], pr0[KSLOTS], pm1[KSLOTS], pr1[KSLOTS];
    {
#pragma unroll
        for (int k = 0; k < KSLOTS; k++) {
            float a0 = 0.f, c0 = 0.f, a1 = 0.f, c1 = 0.f;
            if ((z0 - 2 >= 0) & inb[k]) {
                const size_t g = (size_t)(z0 - 2) * vol + goff[k];
                a0 = Mb[g]; c0 = Rb[g];
            }
            if ((z0 - 1 >= 0) & inb[k]) {
                const size_t g = (size_t)(z0 - 1) * vol + goff[k];
                a1 = Mb[g]; c1 = Rb[g];
            }
            pm0[k] = a0; pr0[k] = c0; pm1[k] = a1; pr1[k] = c1;
        }
    }

    for (int s2 = 0; s2 < NPAIR; s2++) {
        const int bbase = (s2 & 1) * 2;
        float2* const bufA = &mr2[bbase][0][0];
        float2* const bufB = &mr2[bbase + 1][0][0];

        // ---- Commit both prefetched planes (in-bounds slots only) ----
#pragma unroll
        for (int k = 0; k < KSLOTS; k++) {
            if (inb[k]) {
                bufA[soff[k]] = make_float2(pm0[k], pr0[k]);
                bufB[soff[k]] = make_float2(pm1[k], pr1[k]);
            }
        }
        __syncthreads();

        // ---- Prefetch the next two planes ----
        if (s2 < NPAIR - 1) {
            const int zA = z0 + 2 * s2;        // = z0-2 + 2(s2+1)
            const int zB = zA + 1;
            const bool okA = ((unsigned)zA < DD);
            const bool okB = ((unsigned)zB < DD);
#pragma unroll
            for (int k = 0; k < KSLOTS; k++) {
                float a0 = 0.f, c0 = 0.f, a1 = 0.f, c1 = 0.f;
                if (okA & inb[k]) {
                    const size_t g = (size_t)zA * vol + goff[k];
                    a0 = Mb[g]; c0 = Rb[g];
                }
                if (okB & inb[k]) {
                    const size_t g = (size_t)zB * vol + goff[k];
                    a1 = Mb[g]; c1 = Rb[g];
                }
                pm0[k] = a0; pr0[k] = c0; pm1[k] = a1; pr1[k] = c1;
            }
        }

        const int xb = 2 * tx;   // staging col of leftmost halo pair
        const bool emit = (s2 >= 2);

        // ======== Process the two planes (p = 0, 1) ========
#pragma unroll
        for (int p = 0; p < 2; p++) {
            const int bidx = bbase + p;
            const int rpp  = (rp + p >= 5) ? rp + p - 5 : rp + p;

            // Hoist ring-old loads (LDS latency hidden by row filters).
            const float4 oa0 = hista[rpp][y0 + 0][tx];
            const float4 ob0 = histb[rpp][y0 + 0][tx];
            const float2 oc0 = histc[rpp][y0 + 0][tx];
            const float4 oa1 = hista[rpp][y0 + 1][tx];
            const float4 ob1 = histb[rpp][y0 + 1][tx];
            const float2 oc1 = histc[rpp][y0 + 1][tx];

            // H x W filter: W0 = rows 0..4; W1 = W0 - row0 + row5.
            float4 sab0 = make_float4(0.f, 0.f, 0.f, 0.f);
            float4 scd0 = make_float4(0.f, 0.f, 0.f, 0.f);
            float2 se0  = make_float2(0.f, 0.f);
            float4 sab1, scd1;
            float2 se1;
            float4 r0ab = make_float4(0.f, 0.f, 0.f, 0.f);
            float4 r0cd = make_float4(0.f, 0.f, 0.f, 0.f);
            float2 r0e  = make_float2(0.f, 0.f);
#pragma unroll
            for (int j = 0; j < 6; j++) {
                const float2* rowp = &mr2[bidx][y0 + j][xb];
                const float4 q0 = *(const float4*)(rowp);      // m0 r0 m1 r1
                const float4 q1 = *(const float4*)(rowp + 2);  // m2 r2 m3 r3
                const float4 q2 = *(const float4*)(rowp + 4);  // m4 r4 m5 r5
                const float m0 = q0.x, r0 = q0.y, m1 = q0.z, r1 = q0.w;
                const float m2 = q1.x, r2 = q1.y, m3 = q1.z, r3 = q1.w;
                const float m4 = q2.x, r4 = q2.y, m5 = q2.z, r5 = q2.w;

                const float tM  = m1 + m2 + m3 + m4;
                const float tR  = r1 + r2 + r3 + r4;
                const float tMM = fmaf(m1, m1, fmaf(m2, m2, fmaf(m3, m3, m4 * m4)));
                const float tRR = fmaf(r1, r1, fmaf(r2, r2, fmaf(r3, r3, r4 * r4)));
                const float tMR = fmaf(m1, r1, fmaf(m2, r2, fmaf(m3, r3, m4 * r4)));

                const float aM0 = tM + m0,            aM1 = tM + m5;
                const float aR0 = tR + r0,            aR1 = tR + r5;
                const float aMM0 = fmaf(m0, m0, tMM), aMM1 = fmaf(m5, m5, tMM);
                const float aRR0 = fmaf(r0, r0, tRR), aRR1 = fmaf(r5, r5, tRR);
                const float aMR0 = fmaf(m0, r0, tMR), aMR1 = fmaf(m5, r5, tMR);

                if (j == 0) {
                    r0ab = make_float4(aM0, aM1, aR0, aR1);
                    r0cd = make_float4(aMM0, aMM1, aRR0, aRR1);
                    r0e  = make_float2(aMR0, aMR1);
                }
                if (j < 5) {
                    sab0.x += aM0;  sab0.y += aM1;  sab0.z += aR0;  sab0.w += aR1;
                    scd0.x += aMM0; scd0.y += aMM1; scd0.z += aRR0; scd0.w += aRR1;
                    se0.x  += aMR0; se0.y  += aMR1;
                } else {
                    sab1 = make_float4((sab0.x - r0ab.x) + aM0,
                                       (sab0.y - r0ab.y) + aM1,
                                       (sab0.z - r0ab.z) + aR0,
                                       (sab0.w - r0ab.w) + aR1);
                    scd1 = make_float4((scd0.x - r0cd.x) + aMM0,
                                       (scd0.y - r0cd.y) + aMM1,
                                       (scd0.z - r0cd.z) + aRR0,
                                       (scd0.w - r0cd.w) + aRR1);
                    se1  = make_float2((se0.x - r0e.x) + aMR0,
                                       (se0.y - r0e.y) + aMR1);
                }
            }

            // Ring D update + emit, both row groups.
#pragma unroll
            for (int g = 0; g < 2; g++) {
                const float4 s_ab = g ? sab1 : sab0;
                const float4 s_cd = g ? scd1 : scd0;
                const float2 s_e  = g ? se1  : se0;
                const float4 oa = g ? oa1 : oa0;
                const float4 ob = g ? ob1 : ob0;
                const float2 oc = g ? oc1 : oc0;
                runs_ab[g].x += s_ab.x - oa.x; runs_ab[g].y += s_ab.y - oa.y;
                runs_ab[g].z += s_ab.z - oa.z; runs_ab[g].w += s_ab.w - oa.w;
                runs_cd[g].x += s_cd.x - ob.x; runs_cd[g].y += s_cd.y - ob.y;
                runs_cd[g].z += s_cd.z - ob.z; runs_cd[g].w += s_cd.w - ob.w;
                runs_e[g].x  += s_e.x  - oc.x; runs_e[g].y  += s_e.y  - oc.y;
                hista[rpp][y0 + g][tx] = s_ab;
                histb[rpp][y0 + g][tx] = s_cd;
                histc[rpp][y0 + g][tx] = s_e;

                if (emit) {
                    // corr = NUM / (sqrt(A*B) + 0.15625), exact rescale of
                    // the 1/125-normalized formula by 125^2.
#pragma unroll
                    for (int c = 0; c < 2; c++) {
                        const float sM  = c ? runs_ab[g].y : runs_ab[g].x;
                        const float sR  = c ? runs_ab[g].w : runs_ab[g].z;
                        const float sMM = c ? runs_cd[g].y : runs_cd[g].x;
                        const float sRR = c ? runs_cd[g].w : runs_cd[g].z;
                        const float sMR = c ? runs_e[g].y  : runs_e[g].x;

                        const float A   = fmaf(-sM, sM, fmaf(125.f, sMM, 0.15625f));
                        const float B   = fmaf(-sR, sR, fmaf(125.f, sRR, 0.15625f));
                        const float NUM = fmaf(-sM, sR, 125.f * sMR);
                        const float AB  = A * B;
                        const float den = fmaf(AB, rsqrtf(AB), 0.15625f);
                        acc += __fdividef(NUM, den);
                    }
                }
            }
        }

        rp += 2;
        if (rp >= 5) rp -= 5;
    }

    // ---- Block reduction (128 threads) + atomic ----
    __shared__ float warp_sums[NTHR / 32];
    float v = acc;
#pragma unroll
    for (int off = 16; off > 0; off >>= 1)
        v += __shfl_xor_sync(0xFFFFFFFFu, v, off);
    if ((tid & 31) == 0) warp_sums[tid >> 5] = v;
    __syncthreads();
    if (tid < 32) {
        float sWS = (tid < NTHR / 32) ? warp_sums[tid] : 0.f;
#pragma unroll
        for (int off = 2; off > 0; off >>= 1)
            sWS += __shfl_xor_sync(0xFFFFFFFFu, sWS, off);
        if (tid == 0)
            atomicAdd(out, -sWS * (1.0f / (float)NTOT));
    }
}

__global__ void lncc_zero_out(float* out) { out[0] = 0.f; }

// ---------------------------------------------------------------------------
extern "C" void kernel_launch(void* const* d_in, const int* in_sizes, int n_in,
                              void* d_out, int out_size) {
    const float* M = (const float*)d_in[0];
    const float* R = (const float*)d_in[1];
    // d_in[2] is the box kernel (ones/125) — folded into the corr rescale.
    float* out = (float*)d_out;

    lncc_zero_out<<<1, 1>>>(out);

    dim3 blk(TPC, TRH, 1);                                  // (16,8) = 128
    dim3 grd(WW / TW, HH / TH, BATCH * NCHUNK);             // (5,10,8) = 400
    lncc_fused<<<grd, blk>>>(M, R, out);
}